// round 15
// baseline (speedup 1.0000x reference)
#include <cuda_runtime.h>
#include <cuda_fp16.h>
#include <cstdint>

// out[B,N] = x[B,K] @ w[K,N] + bias[N]
// fp16 HMMA m16n8k16 f32-accum. Single launch: full 128x128 tiles + 128x64
// N-split tail. 4 warps/CTA, warp tile 64x64 / 64x32, 2 CTAs/SM.
// Second-sweep CTAs get a ~1300-cycle start delay to anti-phase the two
// co-resident CTAs' barrier bubbles. Fused prepass, uint4 stores both parts.
#define BATCH 4096
#define KDIM  4096
#define NDIM  4096

#define TM 128
#define KC 64          // K elements per stage (128 bytes fp16 per row)
#define THREADS 128    // 4 warps
#define K_ITERS (KDIM / KC)   // 64
#define NTILES 1024           // (4096/128) * (4096/128)

// ---------------- scratch (device globals: allocation-free) ----------------
__device__ __half g_x[(size_t)BATCH * KDIM];
__device__ __half g_w[(size_t)NDIM * KDIM];   // transposed: [n][k]

#define SMEM_TOTAL (3 * (TM + 128) * 128)   // 98304 (full-tile stages)

__device__ __forceinline__ uint32_t smem_u32(const void* p) {
    uint32_t a;
    asm("{ .reg .u64 t; cvta.to.shared.u64 t, %1; cvt.u32.u64 %0, t; }"
        : "=r"(a) : "l"(p));
    return a;
}

__device__ __forceinline__ void cp_async16(uint32_t smaddr, const void* gptr) {
    asm volatile("cp.async.cg.shared.global [%0], [%1], 16;\n"
                 :: "r"(smaddr), "l"(gptr));
}
#define CP_COMMIT() asm volatile("cp.async.commit_group;\n" ::: "memory")
#define CP_WAIT1()  asm volatile("cp.async.wait_group 1;\n" ::: "memory")

__device__ __forceinline__ void ldsm_x4(uint32_t addr, uint32_t& r0, uint32_t& r1,
                                        uint32_t& r2, uint32_t& r3) {
    asm volatile("ldmatrix.sync.aligned.m8n8.x4.shared.b16 {%0,%1,%2,%3}, [%4];"
                 : "=r"(r0), "=r"(r1), "=r"(r2), "=r"(r3) : "r"(addr));
}

__device__ __forceinline__ uint32_t f2h2(float lo, float hi) {
    __half2 h = __floats2half2_rn(lo, hi);
    return *reinterpret_cast<uint32_t*>(&h);
}

__device__ __forceinline__ void mma_16816(float* c, const uint32_t* a,
                                          uint32_t b0, uint32_t b1) {
    asm volatile(
        "mma.sync.aligned.m16n8k16.row.col.f32.f16.f16.f32 "
        "{%0,%1,%2,%3}, {%4,%5,%6,%7}, {%8,%9}, {%0,%1,%2,%3};"
        : "+f"(c[0]), "+f"(c[1]), "+f"(c[2]), "+f"(c[3])
        : "r"(a[0]), "r"(a[1]), "r"(a[2]), "r"(a[3]), "r"(b0), "r"(b1));
}

// ---------------- fused prepass ----------------
// blocks [0, XBLOCKS): convert x, 2x float4 in -> 1x uint4 out per thread
// blocks [XBLOCKS, XBLOCKS+WBLOCKS): 64(k) x 32(n) transpose tiles of w,
//   uint4 stores (full 128B transactions).
#define XBLOCKS (BATCH * KDIM / 8 / 256)        // 8192
#define WBLOCKS ((NDIM / 32) * (KDIM / 64))     // 8192
__global__ void __launch_bounds__(256) prepass_kernel(const float4* __restrict__ x,
                                                      const float* __restrict__ w) {
    __shared__ float tile[64][33];
    int bid = blockIdx.x;
    int tid = threadIdx.x;
    if (bid < XBLOCKS) {
        size_t i = (size_t)bid * 256 + tid;
        float4 v0 = x[2 * i];
        float4 v1 = x[2 * i + 1];
        reinterpret_cast<uint4*>(g_x)[i] =
            make_uint4(f2h2(v0.x, v0.y), f2h2(v0.z, v0.w),
                       f2h2(v1.x, v1.y), f2h2(v1.z, v1.w));
    } else {
        int r = bid - XBLOCKS;
        int o0 = (r & 127) * 32;   // N tile (32 wide)
        int i0 = (r >> 7) * 64;    // K tile (64 deep)
        int c = tid & 31, rr0 = tid >> 5;
        #pragma unroll
        for (int rr = rr0; rr < 64; rr += 8)
            tile[rr][c] = w[(size_t)(i0 + rr) * NDIM + o0 + c];
        __syncthreads();
        int n = tid >> 3, s = tid & 7;   // n 0..31, s 0..7
        uint32_t h0 = f2h2(tile[s * 8 + 0][n], tile[s * 8 + 1][n]);
        uint32_t h1 = f2h2(tile[s * 8 + 2][n], tile[s * 8 + 3][n]);
        uint32_t h2 = f2h2(tile[s * 8 + 4][n], tile[s * 8 + 5][n]);
        uint32_t h3 = f2h2(tile[s * 8 + 6][n], tile[s * 8 + 7][n]);
        *reinterpret_cast<uint4*>(&g_w[(size_t)(o0 + n) * KDIM + i0 + s * 8]) =
            make_uint4(h0, h1, h2, h3);
    }
}

// ---------------- GEMM body (templated on N-tiles per warp) ----------------
// NBT=8: full 128x128 tile (warp 64x64). NBT=4: 128x64 half tile (warp 64x32).
template <int NBT>
__device__ __forceinline__ void gemm_body(uint32_t sb, int tid,
                                          int m0, int n0,
                                          const float* __restrict__ bias,
                                          float* __restrict__ out) {
    constexpr int BROWS = 16 * NBT;
    constexpr int STB   = (TM + BROWS) * 128;
    constexpr int JPT   = (8 + NBT) / 4;   // producer loads per ks

    int lane = tid & 31;
    int wid = tid >> 5;
    int wm = wid & 1;
    int wn = wid >> 1;

    float acc[4][NBT][4];
    #pragma unroll
    for (int i = 0; i < 4; ++i)
        #pragma unroll
        for (int j = 0; j < NBT; ++j)
            #pragma unroll
            for (int k = 0; k < 4; ++k) acc[i][j][k] = 0.f;

    int prow = tid >> 3;
    int pseg = tid & 7;
    const __half* pAk = g_x + (size_t)(m0 + prow) * KDIM + pseg * 8;
    const __half* pBk = g_w + (size_t)(n0 + prow) * KDIM + pseg * 8;
    uint32_t soA[8], soB[NBT];
    #pragma unroll
    for (int j = 0; j < 8; ++j) {
        int rowA = prow + j * 16;
        soA[j] = rowA * 128 + ((pseg ^ (rowA & 7)) << 4);
    }
    #pragma unroll
    for (int j = 0; j < NBT; ++j) {
        int rowB = prow + j * 16;
        soB[j] = TM * 128 + rowB * 128 + ((pseg ^ (rowB & 7)) << 4);
    }

    #define LOAD_STAGE_PART(sp_, j0_, j1_)                                        \
        _Pragma("unroll")                                                          \
        for (int j = (j0_); j < (j1_); ++j) {                                      \
            if (j < 8) cp_async16((sp_) + soA[j], pAk + (size_t)j * 16 * KDIM);    \
            else       cp_async16((sp_) + soB[j - 8], pBk + (size_t)(j - 8) * 16 * KDIM); \
        }

    LOAD_STAGE_PART(sb + 0 * STB, 0, 8 + NBT); CP_COMMIT();
    pAk += KC; pBk += KC;
    LOAD_STAGE_PART(sb + 1 * STB, 0, 8 + NBT); CP_COMMIT();
    pAk += KC; pBk += KC;

    int la = (lane & 15);
    int khalf = lane >> 4;

    uint32_t aBase[4], bBase[NBT / 2];
    #pragma unroll
    for (int mt = 0; mt < 4; ++mt) {
        int row = wm * 64 + mt * 16 + la;
        aBase[mt] = row * 128 + (((row & 7) ^ khalf) << 4);
    }
    #pragma unroll
    for (int q = 0; q < NBT / 2; ++q) {
        int row = wn * (NBT * 8) + q * 16 + la;
        bBase[q] = TM * 128 + row * 128 + (((row & 7) ^ khalf) << 4);
    }

    uint32_t afb[2][4][4];
    uint32_t bfb[2][NBT][2];

    #define LOAD_FRAGS(sa_, ks_, buf_) do {                                       \
        _Pragma("unroll")                                                          \
        for (int q = 0; q < NBT / 2; ++q) {                                       \
            uint32_t addr_ = (sa_) + (bBase[q] ^ ((ks_) << 5));                   \
            uint32_t r0_, r1_, r2_, r3_;                                          \
            ldsm_x4(addr_, r0_, r1_, r2_, r3_);                                   \
            bfb[buf_][2 * q][0] = r0_;     bfb[buf_][2 * q][1] = r2_;             \
            bfb[buf_][2 * q + 1][0] = r1_; bfb[buf_][2 * q + 1][1] = r3_;         \
        }                                                                          \
        _Pragma("unroll")                                                          \
        for (int mt = 0; mt < 4; ++mt) {                                          \
            uint32_t addr_ = (sa_) + (aBase[mt] ^ ((ks_) << 5));                  \
            ldsm_x4(addr_, afb[buf_][mt][0], afb[buf_][mt][1],                    \
                    afb[buf_][mt][2], afb[buf_][mt][3]);                          \
        }                                                                          \
    } while (0)

    #define ITER(CONS, DOLOAD) do {                                               \
        CP_WAIT1();                                                               \
        __syncthreads();                                                          \
        const uint32_t sa_c = sb + (CONS) * STB;                                  \
        const uint32_t sp_c = sb + (((CONS) + 2) % 3) * STB;                      \
        LOAD_FRAGS(sa_c, 0, 0);                                                   \
        _Pragma("unroll")                                                          \
        for (int ks = 0; ks < 4; ++ks) {                                          \
            int buf = ks & 1;                                                     \
            if (ks < 3) LOAD_FRAGS(sa_c, ks + 1, buf ^ 1);                        \
            if (DOLOAD) LOAD_STAGE_PART(sp_c, ks * JPT, ks * JPT + JPT);          \
            _Pragma("unroll")                                                      \
            for (int mt = 0; mt < 4; ++mt)                                        \
                _Pragma("unroll")                                                  \
                for (int nb = 0; nb < NBT; ++nb)                                  \
                    mma_16816(acc[mt][nb], afb[buf][mt],                          \
                              bfb[buf][nb][0], bfb[buf][nb][1]);                  \
        }                                                                          \
        CP_COMMIT();                                                              \
        if (DOLOAD) { pAk += KC; pBk += KC; }                                     \
    } while (0)

    #pragma unroll 1
    for (int blk = 0; blk < 20; ++blk) {
        ITER(0, true);
        ITER(1, true);
        ITER(2, true);
    }
    ITER(0, true);
    ITER(1, true);
    ITER(2, false);
    ITER(0, false);

    // epilogue: bias + store
    float2 bv[NBT];
    #pragma unroll
    for (int nb = 0; nb < NBT; ++nb) {
        int col = n0 + wn * (NBT * 8) + nb * 8 + (lane & 3) * 2;
        bv[nb] = *reinterpret_cast<const float2*>(bias + col);
    }
    #pragma unroll
    for (int mt = 0; mt < 4; ++mt) {
        int gr = m0 + wm * 64 + mt * 16 + (lane >> 2);
        float* r0p = out + (size_t)gr * NDIM;
        float* r1p = r0p + 8 * (size_t)NDIM;
        #pragma unroll
        for (int nb = 0; nb < NBT; ++nb) {
            int col = n0 + wn * (NBT * 8) + nb * 8 + (lane & 3) * 2;
            float2 v0 = make_float2(acc[mt][nb][0] + bv[nb].x,
                                    acc[mt][nb][1] + bv[nb].y);
            float2 v1 = make_float2(acc[mt][nb][2] + bv[nb].x,
                                    acc[mt][nb][3] + bv[nb].y);
            *reinterpret_cast<float2*>(r0p + col) = v0;
            *reinterpret_cast<float2*>(r1p + col) = v1;
        }
    }
    #undef LOAD_STAGE_PART
    #undef LOAD_FRAGS
    #undef ITER
}

// ---------------- single-launch GEMM: full tiles then N-split halves -------
__global__ void __launch_bounds__(THREADS, 2)
gemm_fp16_kernel(const float* __restrict__ bias, float* __restrict__ out,
                 int nfull, int smCount) {
    extern __shared__ char smem[];
    uint32_t sb = smem_u32(smem);
    int tid = threadIdx.x;
    int id = blockIdx.x;

    // De-phase co-resident CTA pairs: wave-1 pair on an SM is (b, b+smCount).
    // Delay the second sweep ~1300 cycles (half an iteration period) so the
    // two CTAs' barrier/LDSM bubbles anti-phase instead of colliding.
    if (((unsigned)id / (unsigned)smCount) & 1u) {
        float v = 1.0f + (float)tid * 1e-7f;
        #pragma unroll 1
        for (int i = 0; i < 325; ++i) v = fmaf(v, 1.000001f, 0.5f);
        if (v == 0.0f)   // never true; keeps the dependent chain alive
            *reinterpret_cast<volatile float*>(smem) = v;
    }

    if (id < nfull) {
        int m0 = (id >> 5) * TM;
        int n0 = (id & 31) * 128;
        gemm_body<8>(sb, tid, m0, n0, bias, out);
    } else {
        int j = id - nfull;
        int tile = nfull + (j >> 1);
        int m0 = (tile >> 5) * TM;
        int n0 = (tile & 31) * 128 + (j & 1) * 64;
        gemm_body<4>(sb, tid, m0, n0, bias, out);
    }
}

// ---------------- launch ----------------
extern "C" void kernel_launch(void* const* d_in, const int* in_sizes, int n_in,
                              void* d_out, int out_size) {
    const float* x    = (const float*)d_in[0];
    const float* w    = (const float*)d_in[1];
    const float* bias = (const float*)d_in[2];
    float* out = (float*)d_out;

    int dev = 0, smCount = 148;
    cudaGetDevice(&dev);
    cudaDeviceGetAttribute(&smCount, cudaDevAttrMultiProcessorCount, dev);
    int cap = 2 * smCount;
    int nfull = (NTILES / cap) * cap;
    int nrem = NTILES - nfull;

    prepass_kernel<<<XBLOCKS + WBLOCKS, 256>>>((const float4*)x, w);

    cudaFuncSetAttribute(gemm_fp16_kernel,
                         cudaFuncAttributeMaxDynamicSharedMemorySize, SMEM_TOTAL);
    gemm_fp16_kernel<<<nfull + 2 * nrem, THREADS, SMEM_TOTAL>>>(bias, out,
                                                                nfull, smCount);
}

// round 16
// speedup vs baseline: 1.0171x; 1.0171x over previous
#include <cuda_runtime.h>
#include <cuda_fp16.h>
#include <cstdint>

// out[B,N] = x[B,K] @ w[K,N] + bias[N]
// fp16 HMMA m16n8k16 f32-accum. Single launch: full 128x128 tiles + 128x64
// N-split tail. 4 warps/CTA, warp tile 64x64 / 64x32, 2 CTAs/SM.
// MMA blocks split around fragment prefetch to keep the tensor queue fed.
// Fused prepass, uint4 stores both parts.
#define BATCH 4096
#define KDIM  4096
#define NDIM  4096

#define TM 128
#define KC 64          // K elements per stage (128 bytes fp16 per row)
#define THREADS 128    // 4 warps
#define K_ITERS (KDIM / KC)   // 64
#define NTILES 1024           // (4096/128) * (4096/128)

// ---------------- scratch (device globals: allocation-free) ----------------
__device__ __half g_x[(size_t)BATCH * KDIM];
__device__ __half g_w[(size_t)NDIM * KDIM];   // transposed: [n][k]

#define SMEM_TOTAL (3 * (TM + 128) * 128)   // 98304 (full-tile stages)

__device__ __forceinline__ uint32_t smem_u32(const void* p) {
    uint32_t a;
    asm("{ .reg .u64 t; cvta.to.shared.u64 t, %1; cvt.u32.u64 %0, t; }"
        : "=r"(a) : "l"(p));
    return a;
}

__device__ __forceinline__ void cp_async16(uint32_t smaddr, const void* gptr) {
    asm volatile("cp.async.cg.shared.global [%0], [%1], 16;\n"
                 :: "r"(smaddr), "l"(gptr));
}
#define CP_COMMIT() asm volatile("cp.async.commit_group;\n" ::: "memory")
#define CP_WAIT1()  asm volatile("cp.async.wait_group 1;\n" ::: "memory")

__device__ __forceinline__ void ldsm_x4(uint32_t addr, uint32_t& r0, uint32_t& r1,
                                        uint32_t& r2, uint32_t& r3) {
    asm volatile("ldmatrix.sync.aligned.m8n8.x4.shared.b16 {%0,%1,%2,%3}, [%4];"
                 : "=r"(r0), "=r"(r1), "=r"(r2), "=r"(r3) : "r"(addr));
}

__device__ __forceinline__ uint32_t f2h2(float lo, float hi) {
    __half2 h = __floats2half2_rn(lo, hi);
    return *reinterpret_cast<uint32_t*>(&h);
}

__device__ __forceinline__ void mma_16816(float* c, const uint32_t* a,
                                          uint32_t b0, uint32_t b1) {
    asm volatile(
        "mma.sync.aligned.m16n8k16.row.col.f32.f16.f16.f32 "
        "{%0,%1,%2,%3}, {%4,%5,%6,%7}, {%8,%9}, {%0,%1,%2,%3};"
        : "+f"(c[0]), "+f"(c[1]), "+f"(c[2]), "+f"(c[3])
        : "r"(a[0]), "r"(a[1]), "r"(a[2]), "r"(a[3]), "r"(b0), "r"(b1));
}

// ---------------- fused prepass ----------------
// blocks [0, XBLOCKS): convert x, 2x float4 in -> 1x uint4 out per thread
// blocks [XBLOCKS, XBLOCKS+WBLOCKS): 64(k) x 32(n) transpose tiles of w,
//   uint4 stores (full 128B transactions).
#define XBLOCKS (BATCH * KDIM / 8 / 256)        // 8192
#define WBLOCKS ((NDIM / 32) * (KDIM / 64))     // 8192
__global__ void __launch_bounds__(256) prepass_kernel(const float4* __restrict__ x,
                                                      const float* __restrict__ w) {
    __shared__ float tile[64][33];
    int bid = blockIdx.x;
    int tid = threadIdx.x;
    if (bid < XBLOCKS) {
        size_t i = (size_t)bid * 256 + tid;
        float4 v0 = x[2 * i];
        float4 v1 = x[2 * i + 1];
        reinterpret_cast<uint4*>(g_x)[i] =
            make_uint4(f2h2(v0.x, v0.y), f2h2(v0.z, v0.w),
                       f2h2(v1.x, v1.y), f2h2(v1.z, v1.w));
    } else {
        int r = bid - XBLOCKS;
        int o0 = (r & 127) * 32;   // N tile (32 wide)
        int i0 = (r >> 7) * 64;    // K tile (64 deep)
        int c = tid & 31, rr0 = tid >> 5;
        #pragma unroll
        for (int rr = rr0; rr < 64; rr += 8)
            tile[rr][c] = w[(size_t)(i0 + rr) * NDIM + o0 + c];
        __syncthreads();
        int n = tid >> 3, s = tid & 7;   // n 0..31, s 0..7
        uint32_t h0 = f2h2(tile[s * 8 + 0][n], tile[s * 8 + 1][n]);
        uint32_t h1 = f2h2(tile[s * 8 + 2][n], tile[s * 8 + 3][n]);
        uint32_t h2 = f2h2(tile[s * 8 + 4][n], tile[s * 8 + 5][n]);
        uint32_t h3 = f2h2(tile[s * 8 + 6][n], tile[s * 8 + 7][n]);
        *reinterpret_cast<uint4*>(&g_w[(size_t)(o0 + n) * KDIM + i0 + s * 8]) =
            make_uint4(h0, h1, h2, h3);
    }
}

// ---------------- GEMM body (templated on N-tiles per warp) ----------------
// NBT=8: full 128x128 tile (warp 64x64). NBT=4: 128x64 half tile (warp 64x32).
template <int NBT>
__device__ __forceinline__ void gemm_body(uint32_t sb, int tid,
                                          int m0, int n0,
                                          const float* __restrict__ bias,
                                          float* __restrict__ out) {
    constexpr int BROWS = 16 * NBT;
    constexpr int STB   = (TM + BROWS) * 128;
    constexpr int JPT   = (8 + NBT) / 4;   // producer loads per ks

    int lane = tid & 31;
    int wid = tid >> 5;
    int wm = wid & 1;
    int wn = wid >> 1;

    float acc[4][NBT][4];
    #pragma unroll
    for (int i = 0; i < 4; ++i)
        #pragma unroll
        for (int j = 0; j < NBT; ++j)
            #pragma unroll
            for (int k = 0; k < 4; ++k) acc[i][j][k] = 0.f;

    int prow = tid >> 3;
    int pseg = tid & 7;
    const __half* pAk = g_x + (size_t)(m0 + prow) * KDIM + pseg * 8;
    const __half* pBk = g_w + (size_t)(n0 + prow) * KDIM + pseg * 8;
    uint32_t soA[8], soB[NBT];
    #pragma unroll
    for (int j = 0; j < 8; ++j) {
        int rowA = prow + j * 16;
        soA[j] = rowA * 128 + ((pseg ^ (rowA & 7)) << 4);
    }
    #pragma unroll
    for (int j = 0; j < NBT; ++j) {
        int rowB = prow + j * 16;
        soB[j] = TM * 128 + rowB * 128 + ((pseg ^ (rowB & 7)) << 4);
    }

    #define LOAD_STAGE_PART(sp_, j0_, j1_)                                        \
        _Pragma("unroll")                                                          \
        for (int j = (j0_); j < (j1_); ++j) {                                      \
            if (j < 8) cp_async16((sp_) + soA[j], pAk + (size_t)j * 16 * KDIM);    \
            else       cp_async16((sp_) + soB[j - 8], pBk + (size_t)(j - 8) * 16 * KDIM); \
        }

    LOAD_STAGE_PART(sb + 0 * STB, 0, 8 + NBT); CP_COMMIT();
    pAk += KC; pBk += KC;
    LOAD_STAGE_PART(sb + 1 * STB, 0, 8 + NBT); CP_COMMIT();
    pAk += KC; pBk += KC;

    int la = (lane & 15);
    int khalf = lane >> 4;

    uint32_t aBase[4], bBase[NBT / 2];
    #pragma unroll
    for (int mt = 0; mt < 4; ++mt) {
        int row = wm * 64 + mt * 16 + la;
        aBase[mt] = row * 128 + (((row & 7) ^ khalf) << 4);
    }
    #pragma unroll
    for (int q = 0; q < NBT / 2; ++q) {
        int row = wn * (NBT * 8) + q * 16 + la;
        bBase[q] = TM * 128 + row * 128 + (((row & 7) ^ khalf) << 4);
    }

    uint32_t afb[2][4][4];
    uint32_t bfb[2][NBT][2];

    #define LOAD_FRAGS(sa_, ks_, buf_) do {                                       \
        _Pragma("unroll")                                                          \
        for (int q = 0; q < NBT / 2; ++q) {                                       \
            uint32_t addr_ = (sa_) + (bBase[q] ^ ((ks_) << 5));                   \
            uint32_t r0_, r1_, r2_, r3_;                                          \
            ldsm_x4(addr_, r0_, r1_, r2_, r3_);                                   \
            bfb[buf_][2 * q][0] = r0_;     bfb[buf_][2 * q][1] = r2_;             \
            bfb[buf_][2 * q + 1][0] = r1_; bfb[buf_][2 * q + 1][1] = r3_;         \
        }                                                                          \
        _Pragma("unroll")                                                          \
        for (int mt = 0; mt < 4; ++mt) {                                          \
            uint32_t addr_ = (sa_) + (aBase[mt] ^ ((ks_) << 5));                  \
            ldsm_x4(addr_, afb[buf_][mt][0], afb[buf_][mt][1],                    \
                    afb[buf_][mt][2], afb[buf_][mt][3]);                          \
        }                                                                          \
    } while (0)

    // MMAs for m-tiles [mt0_, mt1_) of buffer buf_
    #define MMAS_HALF(buf_, mt0_, mt1_)                                            \
        _Pragma("unroll")                                                          \
        for (int mt = (mt0_); mt < (mt1_); ++mt)                                  \
            _Pragma("unroll")                                                      \
            for (int nb = 0; nb < NBT; ++nb)                                      \
                mma_16816(acc[mt][nb], afb[buf_][mt],                             \
                          bfb[buf_][nb][0], bfb[buf_][nb][1]);

    // Per ks: issue half the MMAs first (refill tensor queue), then the
    // next-buffer LDSM prefetch + producer cp.asyncs (latency hidden under
    // queued tensor work), then the remaining MMAs.
    #define ITER(CONS, DOLOAD) do {                                               \
        CP_WAIT1();                                                               \
        __syncthreads();                                                          \
        const uint32_t sa_c = sb + (CONS) * STB;                                  \
        const uint32_t sp_c = sb + (((CONS) + 2) % 3) * STB;                      \
        LOAD_FRAGS(sa_c, 0, 0);                                                   \
        _Pragma("unroll")                                                          \
        for (int ks = 0; ks < 4; ++ks) {                                          \
            int buf = ks & 1;                                                     \
            MMAS_HALF(buf, 0, 2);                                                 \
            if (ks < 3) LOAD_FRAGS(sa_c, ks + 1, buf ^ 1);                        \
            if (DOLOAD) LOAD_STAGE_PART(sp_c, ks * JPT, ks * JPT + JPT);          \
            MMAS_HALF(buf, 2, 4);                                                 \
        }                                                                          \
        CP_COMMIT();                                                              \
        if (DOLOAD) { pAk += KC; pBk += KC; }                                     \
    } while (0)

    #pragma unroll 1
    for (int blk = 0; blk < 20; ++blk) {
        ITER(0, true);
        ITER(1, true);
        ITER(2, true);
    }
    ITER(0, true);
    ITER(1, true);
    ITER(2, false);
    ITER(0, false);

    // epilogue: bias + store
    float2 bv[NBT];
    #pragma unroll
    for (int nb = 0; nb < NBT; ++nb) {
        int col = n0 + wn * (NBT * 8) + nb * 8 + (lane & 3) * 2;
        bv[nb] = *reinterpret_cast<const float2*>(bias + col);
    }
    #pragma unroll
    for (int mt = 0; mt < 4; ++mt) {
        int gr = m0 + wm * 64 + mt * 16 + (lane >> 2);
        float* r0p = out + (size_t)gr * NDIM;
        float* r1p = r0p + 8 * (size_t)NDIM;
        #pragma unroll
        for (int nb = 0; nb < NBT; ++nb) {
            int col = n0 + wn * (NBT * 8) + nb * 8 + (lane & 3) * 2;
            float2 v0 = make_float2(acc[mt][nb][0] + bv[nb].x,
                                    acc[mt][nb][1] + bv[nb].y);
            float2 v1 = make_float2(acc[mt][nb][2] + bv[nb].x,
                                    acc[mt][nb][3] + bv[nb].y);
            *reinterpret_cast<float2*>(r0p + col) = v0;
            *reinterpret_cast<float2*>(r1p + col) = v1;
        }
    }
    #undef LOAD_STAGE_PART
    #undef LOAD_FRAGS
    #undef MMAS_HALF
    #undef ITER
}

// ---------------- single-launch GEMM: full tiles then N-split halves -------
__global__ void __launch_bounds__(THREADS, 2)
gemm_fp16_kernel(const float* __restrict__ bias, float* __restrict__ out,
                 int nfull) {
    extern __shared__ char smem[];
    uint32_t sb = smem_u32(smem);
    int tid = threadIdx.x;
    int id = blockIdx.x;
    if (id < nfull) {
        int m0 = (id >> 5) * TM;
        int n0 = (id & 31) * 128;
        gemm_body<8>(sb, tid, m0, n0, bias, out);
    } else {
        int j = id - nfull;
        int tile = nfull + (j >> 1);
        int m0 = (tile >> 5) * TM;
        int n0 = (tile & 31) * 128 + (j & 1) * 64;
        gemm_body<4>(sb, tid, m0, n0, bias, out);
    }
}

// ---------------- launch ----------------
extern "C" void kernel_launch(void* const* d_in, const int* in_sizes, int n_in,
                              void* d_out, int out_size) {
    const float* x    = (const float*)d_in[0];
    const float* w    = (const float*)d_in[1];
    const float* bias = (const float*)d_in[2];
    float* out = (float*)d_out;

    int dev = 0, smCount = 148;
    cudaGetDevice(&dev);
    cudaDeviceGetAttribute(&smCount, cudaDevAttrMultiProcessorCount, dev);
    int cap = 2 * smCount;
    int nfull = (NTILES / cap) * cap;
    int nrem = NTILES - nfull;

    prepass_kernel<<<XBLOCKS + WBLOCKS, 256>>>((const float4*)x, w);

    cudaFuncSetAttribute(gemm_fp16_kernel,
                         cudaFuncAttributeMaxDynamicSharedMemorySize, SMEM_TOTAL);
    gemm_fp16_kernel<<<nfull + 2 * nrem, THREADS, SMEM_TOTAL>>>(bias, out, nfull);
}

// round 17
// speedup vs baseline: 1.0222x; 1.0050x over previous
#include <cuda_runtime.h>
#include <cuda_fp16.h>
#include <cstdint>

// out[B,N] = x[B,K] @ w[K,N] + bias[N]
// fp16 HMMA m16n8k16 f32-accum. Single launch: full 128x128 tiles + 128x64
// N-split tail. 4 warps/CTA, warp tile 64x64 / 64x32, 2 CTAs/SM.
// Rotated pipeline: barrier + cp.async wait + next-iteration ks0 fragment
// prefetch are all hidden under the ks=3 MMA block, so each iteration opens
// directly with MMAs. Fused prepass, uint4 stores both parts.
#define BATCH 4096
#define KDIM  4096
#define NDIM  4096

#define TM 128
#define KC 64          // K elements per stage (128 bytes fp16 per row)
#define THREADS 128    // 4 warps
#define K_ITERS (KDIM / KC)   // 64
#define NTILES 1024           // (4096/128) * (4096/128)

// ---------------- scratch (device globals: allocation-free) ----------------
__device__ __half g_x[(size_t)BATCH * KDIM];
__device__ __half g_w[(size_t)NDIM * KDIM];   // transposed: [n][k]

#define SMEM_TOTAL (3 * (TM + 128) * 128)   // 98304 (full-tile stages)

__device__ __forceinline__ uint32_t smem_u32(const void* p) {
    uint32_t a;
    asm("{ .reg .u64 t; cvta.to.shared.u64 t, %1; cvt.u32.u64 %0, t; }"
        : "=r"(a) : "l"(p));
    return a;
}

__device__ __forceinline__ void cp_async16(uint32_t smaddr, const void* gptr) {
    asm volatile("cp.async.cg.shared.global [%0], [%1], 16;\n"
                 :: "r"(smaddr), "l"(gptr));
}
#define CP_COMMIT() asm volatile("cp.async.commit_group;\n" ::: "memory")
#define CP_WAIT1()  asm volatile("cp.async.wait_group 1;\n" ::: "memory")
#define CP_WAIT0()  asm volatile("cp.async.wait_group 0;\n" ::: "memory")

__device__ __forceinline__ void ldsm_x4(uint32_t addr, uint32_t& r0, uint32_t& r1,
                                        uint32_t& r2, uint32_t& r3) {
    asm volatile("ldmatrix.sync.aligned.m8n8.x4.shared.b16 {%0,%1,%2,%3}, [%4];"
                 : "=r"(r0), "=r"(r1), "=r"(r2), "=r"(r3) : "r"(addr));
}

__device__ __forceinline__ uint32_t f2h2(float lo, float hi) {
    __half2 h = __floats2half2_rn(lo, hi);
    return *reinterpret_cast<uint32_t*>(&h);
}

__device__ __forceinline__ void mma_16816(float* c, const uint32_t* a,
                                          uint32_t b0, uint32_t b1) {
    asm volatile(
        "mma.sync.aligned.m16n8k16.row.col.f32.f16.f16.f32 "
        "{%0,%1,%2,%3}, {%4,%5,%6,%7}, {%8,%9}, {%0,%1,%2,%3};"
        : "+f"(c[0]), "+f"(c[1]), "+f"(c[2]), "+f"(c[3])
        : "r"(a[0]), "r"(a[1]), "r"(a[2]), "r"(a[3]), "r"(b0), "r"(b1));
}

// ---------------- fused prepass ----------------
// blocks [0, XBLOCKS): convert x, 2x float4 in -> 1x uint4 out per thread
// blocks [XBLOCKS, XBLOCKS+WBLOCKS): 64(k) x 32(n) transpose tiles of w,
//   uint4 stores (full 128B transactions).
#define XBLOCKS (BATCH * KDIM / 8 / 256)        // 8192
#define WBLOCKS ((NDIM / 32) * (KDIM / 64))     // 8192
__global__ void __launch_bounds__(256) prepass_kernel(const float4* __restrict__ x,
                                                      const float* __restrict__ w) {
    __shared__ float tile[64][33];
    int bid = blockIdx.x;
    int tid = threadIdx.x;
    if (bid < XBLOCKS) {
        size_t i = (size_t)bid * 256 + tid;
        float4 v0 = x[2 * i];
        float4 v1 = x[2 * i + 1];
        reinterpret_cast<uint4*>(g_x)[i] =
            make_uint4(f2h2(v0.x, v0.y), f2h2(v0.z, v0.w),
                       f2h2(v1.x, v1.y), f2h2(v1.z, v1.w));
    } else {
        int r = bid - XBLOCKS;
        int o0 = (r & 127) * 32;   // N tile (32 wide)
        int i0 = (r >> 7) * 64;    // K tile (64 deep)
        int c = tid & 31, rr0 = tid >> 5;
        #pragma unroll
        for (int rr = rr0; rr < 64; rr += 8)
            tile[rr][c] = w[(size_t)(i0 + rr) * NDIM + o0 + c];
        __syncthreads();
        int n = tid >> 3, s = tid & 7;   // n 0..31, s 0..7
        uint32_t h0 = f2h2(tile[s * 8 + 0][n], tile[s * 8 + 1][n]);
        uint32_t h1 = f2h2(tile[s * 8 + 2][n], tile[s * 8 + 3][n]);
        uint32_t h2 = f2h2(tile[s * 8 + 4][n], tile[s * 8 + 5][n]);
        uint32_t h3 = f2h2(tile[s * 8 + 6][n], tile[s * 8 + 7][n]);
        *reinterpret_cast<uint4*>(&g_w[(size_t)(o0 + n) * KDIM + i0 + s * 8]) =
            make_uint4(h0, h1, h2, h3);
    }
}

// ---------------- GEMM body (templated on N-tiles per warp) ----------------
// NBT=8: full 128x128 tile (warp 64x64). NBT=4: 128x64 half tile (warp 64x32).
template <int NBT>
__device__ __forceinline__ void gemm_body(uint32_t sb, int tid,
                                          int m0, int n0,
                                          const float* __restrict__ bias,
                                          float* __restrict__ out) {
    constexpr int BROWS = 16 * NBT;
    constexpr int STB   = (TM + BROWS) * 128;
    constexpr int JPT   = (8 + NBT) / 4;   // producer loads per ks

    int lane = tid & 31;
    int wid = tid >> 5;
    int wm = wid & 1;
    int wn = wid >> 1;

    float acc[4][NBT][4];
    #pragma unroll
    for (int i = 0; i < 4; ++i)
        #pragma unroll
        for (int j = 0; j < NBT; ++j)
            #pragma unroll
            for (int k = 0; k < 4; ++k) acc[i][j][k] = 0.f;

    int prow = tid >> 3;
    int pseg = tid & 7;
    const __half* pAk = g_x + (size_t)(m0 + prow) * KDIM + pseg * 8;
    const __half* pBk = g_w + (size_t)(n0 + prow) * KDIM + pseg * 8;
    uint32_t soA[8], soB[NBT];
    #pragma unroll
    for (int j = 0; j < 8; ++j) {
        int rowA = prow + j * 16;
        soA[j] = rowA * 128 + ((pseg ^ (rowA & 7)) << 4);
    }
    #pragma unroll
    for (int j = 0; j < NBT; ++j) {
        int rowB = prow + j * 16;
        soB[j] = TM * 128 + rowB * 128 + ((pseg ^ (rowB & 7)) << 4);
    }

    #define LOAD_STAGE_PART(sp_, j0_, j1_)                                        \
        _Pragma("unroll")                                                          \
        for (int j = (j0_); j < (j1_); ++j) {                                      \
            if (j < 8) cp_async16((sp_) + soA[j], pAk + (size_t)j * 16 * KDIM);    \
            else       cp_async16((sp_) + soB[j - 8], pBk + (size_t)(j - 8) * 16 * KDIM); \
        }

    LOAD_STAGE_PART(sb + 0 * STB, 0, 8 + NBT); CP_COMMIT();
    pAk += KC; pBk += KC;
    LOAD_STAGE_PART(sb + 1 * STB, 0, 8 + NBT); CP_COMMIT();
    pAk += KC; pBk += KC;

    int la = (lane & 15);
    int khalf = lane >> 4;

    uint32_t aBase[4], bBase[NBT / 2];
    #pragma unroll
    for (int mt = 0; mt < 4; ++mt) {
        int row = wm * 64 + mt * 16 + la;
        aBase[mt] = row * 128 + (((row & 7) ^ khalf) << 4);
    }
    #pragma unroll
    for (int q = 0; q < NBT / 2; ++q) {
        int row = wn * (NBT * 8) + q * 16 + la;
        bBase[q] = TM * 128 + row * 128 + (((row & 7) ^ khalf) << 4);
    }

    uint32_t afb[2][4][4];
    uint32_t bfb[2][NBT][2];

    #define LOAD_FRAGS(sa_, ks_, buf_) do {                                       \
        _Pragma("unroll")                                                          \
        for (int q = 0; q < NBT / 2; ++q) {                                       \
            uint32_t addr_ = (sa_) + (bBase[q] ^ ((ks_) << 5));                   \
            uint32_t r0_, r1_, r2_, r3_;                                          \
            ldsm_x4(addr_, r0_, r1_, r2_, r3_);                                   \
            bfb[buf_][2 * q][0] = r0_;     bfb[buf_][2 * q][1] = r2_;             \
            bfb[buf_][2 * q + 1][0] = r1_; bfb[buf_][2 * q + 1][1] = r3_;         \
        }                                                                          \
        _Pragma("unroll")                                                          \
        for (int mt = 0; mt < 4; ++mt) {                                          \
            uint32_t addr_ = (sa_) + (aBase[mt] ^ ((ks_) << 5));                  \
            ldsm_x4(addr_, afb[buf_][mt][0], afb[buf_][mt][1],                    \
                    afb[buf_][mt][2], afb[buf_][mt][3]);                          \
        }                                                                          \
    } while (0)

    #define MMAS_HALF(buf_, mt0_, mt1_)                                            \
        _Pragma("unroll")                                                          \
        for (int mt = (mt0_); mt < (mt1_); ++mt)                                  \
            _Pragma("unroll")                                                      \
            for (int nb = 0; nb < NBT; ++nb)                                      \
                mma_16816(acc[mt][nb], afb[buf_][mt],                             \
                          bfb[buf_][nb][0], bfb[buf_][nb][1]);

    // Rotated iteration. Entered with ks0 fragments already in buf0.
    // PRE: mid-ks3, wait next stage + barrier + prefetch next iter's ks0.
    // Stage-read protection: last read of stage CONS is LOAD_FRAGS(ks=3) in
    // the ks=2 section; the bar in ks=3 covers it for next iter's producers.
    #define ITER(CONS, DOLOAD, PRE) do {                                          \
        const uint32_t sa_c = sb + (CONS) * STB;                                  \
        const uint32_t sp_c = sb + (((CONS) + 2) % 3) * STB;                      \
        const uint32_t sa_n = sb + (((CONS) + 1) % 3) * STB;                      \
        /* ks = 0 */                                                              \
        MMAS_HALF(0, 0, 2);                                                       \
        LOAD_FRAGS(sa_c, 1, 1);                                                   \
        if (DOLOAD) LOAD_STAGE_PART(sp_c, 0, JPT);                                \
        MMAS_HALF(0, 2, 4);                                                       \
        /* ks = 1 */                                                              \
        MMAS_HALF(1, 0, 2);                                                       \
        LOAD_FRAGS(sa_c, 2, 0);                                                   \
        if (DOLOAD) LOAD_STAGE_PART(sp_c, JPT, 2 * JPT);                          \
        MMAS_HALF(1, 2, 4);                                                       \
        /* ks = 2 */                                                              \
        MMAS_HALF(0, 0, 2);                                                       \
        LOAD_FRAGS(sa_c, 3, 1);                                                   \
        if (DOLOAD) LOAD_STAGE_PART(sp_c, 2 * JPT, 3 * JPT);                      \
        MMAS_HALF(0, 2, 4);                                                       \
        /* ks = 3: hide wait + bar + next-iter ks0 prefetch under MMAs */         \
        MMAS_HALF(1, 0, 2);                                                       \
        if (PRE) {                                                                \
            CP_WAIT0();                                                           \
            __syncthreads();                                                      \
            LOAD_FRAGS(sa_n, 0, 0);                                               \
        }                                                                          \
        if (DOLOAD) {                                                             \
            LOAD_STAGE_PART(sp_c, 3 * JPT, 4 * JPT);                              \
            CP_COMMIT();                                                          \
        }                                                                          \
        MMAS_HALF(1, 2, 4);                                                       \
        if (DOLOAD) { pAk += KC; pBk += KC; }                                     \
    } while (0)

    // prologue: wait stage 0, preload its ks0 fragments
    CP_WAIT1();
    __syncthreads();
    LOAD_FRAGS(sb + 0 * STB, 0, 0);

    // iters 0..59 (all loading), then 60,61 loading, 62 drain+prefetch, 63 last
    #pragma unroll 1
    for (int blk = 0; blk < 20; ++blk) {
        ITER(0, true, true);
        ITER(1, true, true);
        ITER(2, true, true);
    }
    ITER(0, true, true);
    ITER(1, true, true);
    ITER(2, false, true);
    ITER(0, false, false);

    // epilogue: bias + store
    float2 bv[NBT];
    #pragma unroll
    for (int nb = 0; nb < NBT; ++nb) {
        int col = n0 + wn * (NBT * 8) + nb * 8 + (lane & 3) * 2;
        bv[nb] = *reinterpret_cast<const float2*>(bias + col);
    }
    #pragma unroll
    for (int mt = 0; mt < 4; ++mt) {
        int gr = m0 + wm * 64 + mt * 16 + (lane >> 2);
        float* r0p = out + (size_t)gr * NDIM;
        float* r1p = r0p + 8 * (size_t)NDIM;
        #pragma unroll
        for (int nb = 0; nb < NBT; ++nb) {
            int col = n0 + wn * (NBT * 8) + nb * 8 + (lane & 3) * 2;
            float2 v0 = make_float2(acc[mt][nb][0] + bv[nb].x,
                                    acc[mt][nb][1] + bv[nb].y);
            float2 v1 = make_float2(acc[mt][nb][2] + bv[nb].x,
                                    acc[mt][nb][3] + bv[nb].y);
            *reinterpret_cast<float2*>(r0p + col) = v0;
            *reinterpret_cast<float2*>(r1p + col) = v1;
        }
    }
    #undef LOAD_STAGE_PART
    #undef LOAD_FRAGS
    #undef MMAS_HALF
    #undef ITER
}

// ---------------- single-launch GEMM: full tiles then N-split halves -------
__global__ void __launch_bounds__(THREADS, 2)
gemm_fp16_kernel(const float* __restrict__ bias, float* __restrict__ out,
                 int nfull) {
    extern __shared__ char smem[];
    uint32_t sb = smem_u32(smem);
    int tid = threadIdx.x;
    int id = blockIdx.x;
    if (id < nfull) {
        int m0 = (id >> 5) * TM;
        int n0 = (id & 31) * 128;
        gemm_body<8>(sb, tid, m0, n0, bias, out);
    } else {
        int j = id - nfull;
        int tile = nfull + (j >> 1);
        int m0 = (tile >> 5) * TM;
        int n0 = (tile & 31) * 128 + (j & 1) * 64;
        gemm_body<4>(sb, tid, m0, n0, bias, out);
    }
}

// ---------------- launch ----------------
extern "C" void kernel_launch(void* const* d_in, const int* in_sizes, int n_in,
                              void* d_out, int out_size) {
    const float* x    = (const float*)d_in[0];
    const float* w    = (const float*)d_in[1];
    const float* bias = (const float*)d_in[2];
    float* out = (float*)d_out;

    int dev = 0, smCount = 148;
    cudaGetDevice(&dev);
    cudaDeviceGetAttribute(&smCount, cudaDevAttrMultiProcessorCount, dev);
    int cap = 2 * smCount;
    int nfull = (NTILES / cap) * cap;
    int nrem = NTILES - nfull;

    prepass_kernel<<<XBLOCKS + WBLOCKS, 256>>>((const float4*)x, w);

    cudaFuncSetAttribute(gemm_fp16_kernel,
                         cudaFuncAttributeMaxDynamicSharedMemorySize, SMEM_TOTAL);
    gemm_fp16_kernel<<<nfull + 2 * nrem, THREADS, SMEM_TOTAL>>>(bias, out, nfull);
}